// round 13
// baseline (speedup 1.0000x reference)
#include <cuda_runtime.h>
#include <cuda_fp16.h>
#include <math.h>
#include <stdint.h>

#define BB   4
#define SS   2048
#define DD   1024
#define HH   16
#define DKK  64
#define DFFC 4096
#define NTOK (BB*SS)
#define QKLD (2*DD)

// ---------------------------------------------------------------------------
// Scratch (allocation-free rule: __device__ globals)
// ---------------------------------------------------------------------------
__device__ __half g_hidden[(size_t)NTOK*DD];
__device__ __half g_qk    [(size_t)NTOK*QKLD];
__device__ __half g_attn  [(size_t)NTOK*DD];
__device__ float  g_x2    [(size_t)NTOK*DD];
__device__ __half g_h2    [(size_t)NTOK*DD];
__device__ __half g_ffn   [(size_t)NTOK*DFFC];
__device__ __half g_wqkT[(size_t)QKLD*DD];
__device__ __half g_woT [(size_t)DD*DD];
__device__ __half g_w1T [(size_t)DFFC*DD];
__device__ __half g_w2T [(size_t)DD*DFFC];
__device__ float  g_bqk [QKLD];

// ---------------------------------------------------------------------------
// Helpers
// ---------------------------------------------------------------------------
__device__ __forceinline__ uint32_t smem_u32(const void* p) {
    uint32_t a;
    asm("{ .reg .u64 t; cvta.to.shared.u64 t, %1; cvt.u32.u64 %0, t; }"
        : "=r"(a) : "l"(p));
    return a;
}

__device__ __forceinline__ void ldsm4(uint32_t& r0, uint32_t& r1,
                                      uint32_t& r2, uint32_t& r3, uint32_t addr) {
    asm volatile("ldmatrix.sync.aligned.m8n8.x4.shared.b16 {%0,%1,%2,%3}, [%4];"
                 : "=r"(r0), "=r"(r1), "=r"(r2), "=r"(r3) : "r"(addr));
}

__device__ __forceinline__ void ldsm4t(uint32_t& r0, uint32_t& r1,
                                       uint32_t& r2, uint32_t& r3, uint32_t addr) {
    asm volatile("ldmatrix.sync.aligned.m8n8.x4.trans.shared.b16 {%0,%1,%2,%3}, [%4];"
                 : "=r"(r0), "=r"(r1), "=r"(r2), "=r"(r3) : "r"(addr));
}

__device__ __forceinline__ void mma_f16(float* c, const uint32_t* a, const uint32_t* b) {
    asm volatile(
        "mma.sync.aligned.m16n8k16.row.col.f32.f16.f16.f32 "
        "{%0,%1,%2,%3}, {%4,%5,%6,%7}, {%8,%9}, {%0,%1,%2,%3};"
        : "+f"(c[0]), "+f"(c[1]), "+f"(c[2]), "+f"(c[3])
        : "r"(a[0]), "r"(a[1]), "r"(a[2]), "r"(a[3]), "r"(b[0]), "r"(b[1]));
}

__device__ __forceinline__ uint32_t packh2(float lo, float hi) {
    __half2 h = __floats2half2_rn(lo, hi);
    return *(uint32_t*)&h;
}

__device__ __forceinline__ void cpa16(uint32_t dst, const void* src) {
    asm volatile("cp.async.cg.shared.global [%0], [%1], 16;"
                 :: "r"(dst), "l"(src) : "memory");
}
#define CPA_COMMIT() asm volatile("cp.async.commit_group;" ::: "memory")
#define CPA_WAIT1()  asm volatile("cp.async.wait_group 1;"  ::: "memory")
#define CPA_WAIT0()  asm volatile("cp.async.wait_group 0;"  ::: "memory")

// ---------------------------------------------------------------------------
// Fused prep: 5 weight transposes (WT[n][k] = half(W[k][n])) + bias concat
// ---------------------------------------------------------------------------
__global__ void __launch_bounds__(256) prep_kernel(
    const float* __restrict__ Wq, const float* __restrict__ Wk,
    const float* __restrict__ Wo, const float* __restrict__ W1,
    const float* __restrict__ W2, const float* __restrict__ bq,
    const float* __restrict__ bk,
    __half* __restrict__ wqkT, __half* __restrict__ woT,
    __half* __restrict__ w1T,  __half* __restrict__ w2T,
    float* __restrict__ bqk)
{
    __shared__ float tile[32][33];
    int t = blockIdx.x;
    const float* W; __half* WT; int K, N;
    if (t < 1024)      { W = Wq; WT = wqkT;                   K = DD;   N = DD; }
    else if (t < 2048) { W = Wk; WT = wqkT + (size_t)DD*DD;   K = DD;   N = DD;   t -= 1024; }
    else if (t < 3072) { W = Wo; WT = woT;                    K = DD;   N = DD;   t -= 2048; }
    else if (t < 7168) { W = W1; WT = w1T;                    K = DD;   N = DFFC; t -= 3072; }
    else if (t < 11264){ W = W2; WT = w2T;                    K = DFFC; N = DD;   t -= 7168; }
    else {
        int i = threadIdx.x;
#pragma unroll
        for (int r = 0; r < 8; r++, i += 256) {
            if (i < DD) bqk[i] = bq[i];
            else        bqk[i] = bk[i - DD];
        }
        return;
    }
    int ntx = N >> 5;
    int kb = (t / ntx) * 32, nb = (t % ntx) * 32;
    int tx = threadIdx.x & 31, ty = threadIdx.x >> 5;
#pragma unroll
    for (int i = 0; i < 32; i += 8)
        tile[ty + i][tx] = W[(size_t)(kb + ty + i) * N + nb + tx];
    __syncthreads();
#pragma unroll
    for (int i = 0; i < 32; i += 8)
        WT[(size_t)(nb + ty + i) * K + kb + tx] = __float2half(tile[tx][ty + i]);
}
#define PREP_BLOCKS 11265

// ---------------------------------------------------------------------------
// Pipelined fp16 tensor-core GEMM (R11-exact: 3-stage cp.async, 96KB, 2 CTA/SM)
// ---------------------------------------------------------------------------
__global__ void __launch_bounds__(128, 2) tc_gemm_kernel(
    const __half* __restrict__ A, const __half* __restrict__ BT,
    const float* __restrict__ bias, const float* __restrict__ res,
    float* __restrict__ Cf, __half* __restrict__ Ch,
    int M, int N, int K, int epi)
{
    extern __shared__ char dsm[];
    const uint32_t sAu = smem_u32(dsm);
    const uint32_t sBu = sAu + 3 * 16384;

    const int tid  = threadIdx.x;
    const int lane = tid & 31;
    const int wid  = tid >> 5;
    const int wm   = wid & 1;
    const int wn   = wid >> 1;
    const int m0   = blockIdx.y * 128;
    const int n0   = blockIdx.x * 128;

    float acc[4][8][4];
#pragma unroll
    for (int mt = 0; mt < 4; mt++)
#pragma unroll
        for (int nt = 0; nt < 8; nt++)
#pragma unroll
            for (int i = 0; i < 4; i++) acc[mt][nt][i] = 0.f;

    int r_[8], c_[8];
    uint32_t stoff[8];
#pragma unroll
    for (int i = 0; i < 8; i++) {
        int v = tid + i * 128;
        r_[i] = v >> 3;
        c_[i] = v & 7;
        stoff[i] = (uint32_t)(r_[i] * 128 + ((c_[i] ^ (r_[i] & 7)) << 4));
    }

    const __half* Ag = A  + (size_t)m0 * K;
    const __half* Bg = BT + (size_t)n0 * K;
    const int nkt = K >> 6;

#pragma unroll
    for (int p = 0; p < 2; p++) {
        uint32_t ab = sAu + p * 16384, bb = sBu + p * 16384;
        const __half* Ag2 = Ag + p * 64;
        const __half* Bg2 = Bg + p * 64;
#pragma unroll
        for (int i = 0; i < 8; i++) {
            cpa16(ab + stoff[i], Ag2 + (size_t)r_[i] * K + c_[i] * 8);
            cpa16(bb + stoff[i], Bg2 + (size_t)r_[i] * K + c_[i] * 8);
        }
        CPA_COMMIT();
    }

    const int q  = lane >> 3;
    const int r8 = lane & 7;
    int mA[4], nB[4];
#pragma unroll
    for (int mt = 0; mt < 4; mt++) mA[mt] = wm * 64 + mt * 16 + (q & 1) * 8 + r8;
#pragma unroll
    for (int nt2 = 0; nt2 < 4; nt2++) nB[nt2] = wn * 64 + nt2 * 16 + (q >> 1) * 8 + r8;

    int stg = 0;
    for (int kt = 0; kt < nkt; kt++) {
        CPA_WAIT1();
        __syncthreads();

        {
            int kt2 = kt + 2;
            if (kt2 < nkt) {
                int s2 = stg + 2; if (s2 >= 3) s2 -= 3;
                uint32_t ab = sAu + s2 * 16384, bb = sBu + s2 * 16384;
                const __half* Ag2 = Ag + kt2 * 64;
                const __half* Bg2 = Bg + kt2 * 64;
#pragma unroll
                for (int i = 0; i < 8; i++) {
                    cpa16(ab + stoff[i], Ag2 + (size_t)r_[i] * K + c_[i] * 8);
                    cpa16(bb + stoff[i], Bg2 + (size_t)r_[i] * K + c_[i] * 8);
                }
            }
            CPA_COMMIT();
        }

        const uint32_t sAb = sAu + stg * 16384;
        const uint32_t sBb = sBu + stg * 16384;
#pragma unroll
        for (int ks = 0; ks < 4; ks++) {
            uint32_t af[4][4];
#pragma unroll
            for (int mt = 0; mt < 4; mt++) {
                int g16 = ks * 2 + (q >> 1);
                uint32_t ad = sAb + (uint32_t)(mA[mt] * 128 + ((g16 ^ (mA[mt] & 7)) << 4));
                ldsm4(af[mt][0], af[mt][1], af[mt][2], af[mt][3], ad);
            }
            uint32_t bf[8][2];
#pragma unroll
            for (int nt2 = 0; nt2 < 4; nt2++) {
                int g16 = ks * 2 + (q & 1);
                uint32_t bd = sBb + (uint32_t)(nB[nt2] * 128 + ((g16 ^ (nB[nt2] & 7)) << 4));
                ldsm4(bf[nt2*2][0], bf[nt2*2][1], bf[nt2*2+1][0], bf[nt2*2+1][1], bd);
            }
#pragma unroll
            for (int mt = 0; mt < 4; mt++)
#pragma unroll
                for (int nt = 0; nt < 8; nt++)
                    mma_f16(acc[mt][nt], af[mt], bf[nt]);
        }
        stg++; if (stg == 3) stg = 0;
    }

    const int g   = lane >> 2;
    const int tig = lane & 3;
#pragma unroll
    for (int mt = 0; mt < 4; mt++) {
#pragma unroll
        for (int h = 0; h < 2; h++) {
            int row = m0 + wm * 64 + mt * 16 + h * 8 + g;
            size_t rbase = (size_t)row * N;
#pragma unroll
            for (int nt = 0; nt < 8; nt++) {
                int col = n0 + wn * 64 + nt * 8 + tig * 2;
                float v0 = acc[mt][nt][h*2 + 0] + bias[col];
                float v1 = acc[mt][nt][h*2 + 1] + bias[col + 1];
                if (epi == 2) {
                    v0 = 0.5f * v0 * (1.0f + erff(v0 * 0.70710678118654752440f));
                    v1 = 0.5f * v1 * (1.0f + erff(v1 * 0.70710678118654752440f));
                    *(__half2*)(Ch + rbase + col) = __floats2half2_rn(v0, v1);
                } else if (epi == 1) {
                    v0 += res[rbase + col];
                    v1 += res[rbase + col + 1];
                    float2 o2 = { v0, v1 };
                    *(float2*)(Cf + rbase + col) = o2;
                } else {
                    *(__half2*)(Ch + rbase + col) = __floats2half2_rn(v0, v1);
                }
            }
        }
    }
}
#define GEMM_SMEM (3*16384*2)

// ---------------------------------------------------------------------------
// LayerNorm: fp32 in -> fp16 out (unchanged)
// ---------------------------------------------------------------------------
__global__ void __launch_bounds__(256) ln_kernel(
    const float* __restrict__ x, const float* __restrict__ g,
    const float* __restrict__ b, __half* __restrict__ out)
{
    __shared__ float red[20];
    int t = blockIdx.x;
    int tid = threadIdx.x;
    float4 v = ((const float4*)(x + (size_t)t*DD))[tid];
    float s  = v.x + v.y + v.z + v.w;
    float s2 = v.x*v.x + v.y*v.y + v.z*v.z + v.w*v.w;
#pragma unroll
    for (int o = 16; o; o >>= 1) {
        s  += __shfl_xor_sync(0xffffffffu, s,  o);
        s2 += __shfl_xor_sync(0xffffffffu, s2, o);
    }
    int w = tid >> 5, l = tid & 31;
    if (l == 0) { red[w] = s; red[8 + w] = s2; }
    __syncthreads();
    if (tid == 0) {
        float a = 0.f, c = 0.f;
#pragma unroll
        for (int i = 0; i < 8; i++) { a += red[i]; c += red[8 + i]; }
        red[16] = a; red[17] = c;
    }
    __syncthreads();
    float mean = red[16] * (1.0f / DD);
    float var  = red[17] * (1.0f / DD) - mean * mean;
    float inv  = rsqrtf(var + 1e-5f);
    float4 gv = ((const float4*)g)[tid];
    float4 bv = ((const float4*)b)[tid];
    __half2* op = (__half2*)(out + (size_t)t*DD) + 2*tid;
    op[0] = __floats2half2_rn((v.x - mean) * inv * gv.x + bv.x,
                              (v.y - mean) * inv * gv.y + bv.y);
    op[1] = __floats2half2_rn((v.z - mean) * inv * gv.z + bv.z,
                              (v.w - mean) * inv * gv.w + bv.w);
}

// ---------------------------------------------------------------------------
// fp16 tensor-core flash attention v5. values == K (reference quirk).
// R11 base (4 warps x 32q, 32-key tiles) with DEFERRED l-reduction:
// per-thread partial sums carry the corr recurrence (corr is row-uniform,
// so linearity holds); the cross-lane shfl-sum happens once in the epilogue.
// Removes 2 shfls per (mt,hh) per tile from the softmax dependent chain.
// ---------------------------------------------------------------------------
__global__ void __launch_bounds__(128, 3) tc_attn_kernel(
    const __half* __restrict__ QK, const int* __restrict__ mask,
    __half* __restrict__ O)
{
    extern __shared__ char dsm[];
    __half* Qs = (__half*)dsm;                  // [128][64]
    __half* Kj = (__half*)(dsm + 16384);        // [2][32*64]
    int*    msk = (int*)(dsm + 24576);          // [2][32]

    const int b = blockIdx.z, h = blockIdx.y;
    const int q0 = blockIdx.x * 128;
    const int tid = threadIdx.x;
    const int lane = tid & 31, wid = tid >> 5;
    const size_t base_q = (size_t)b * SS * QKLD + (size_t)h * DKK;
    const size_t base_k = base_q + DD;
    const size_t base_o = (size_t)b * SS * DD + (size_t)h * DKK;

    const uint32_t sQ = smem_u32(Qs);
    const uint32_t sK = smem_u32(Kj);
    const uint32_t sM = smem_u32(msk);

    // Q tile: 128 rows x 8 chunks (16B)
#pragma unroll
    for (int i = 0; i < 8; i++) {
        int v = tid + i * 128;
        int r = v >> 3, c = v & 7;
        float4 val = *(const float4*)(QK + base_q + (size_t)(q0 + r) * QKLD + c * 8);
        *(float4*)((char*)Qs + r * 128 + ((c ^ (r & 7)) << 4)) = val;
    }

    // prologue: async K tile 0 + mask 0
#pragma unroll
    for (int i = 0; i < 2; i++) {
        int v = tid + i * 128;
        int j = v >> 3, c = v & 7;
        cpa16(sK + (uint32_t)(j * 128 + ((c ^ (j & 7)) << 4)),
              QK + base_k + (size_t)j * QKLD + c * 8);
    }
    if (tid < 8) cpa16(sM + tid * 16, mask + b * SS + tid * 4);
    CPA_COMMIT();

    const int q  = lane >> 3, r8 = lane & 7;
    const int g  = lane >> 2, tig = lane & 3;
    const int t2 = 2 * tig;
    const int grp = lane >> 3, li = lane & 7;
    int mA[2];
    mA[0] = wid * 32 + (q & 1) * 8 + r8;
    mA[1] = mA[0] + 16;

    float m_[2][2], l_[2][2];
#pragma unroll
    for (int mt = 0; mt < 2; mt++)
#pragma unroll
        for (int hh = 0; hh < 2; hh++) { m_[mt][hh] = -INFINITY; l_[mt][hh] = 0.f; }
    float accO[2][8][4];
#pragma unroll
    for (int mt = 0; mt < 2; mt++)
#pragma unroll
        for (int nt = 0; nt < 8; nt++)
#pragma unroll
            for (int i = 0; i < 4; i++) accO[mt][nt][i] = 0.f;

    int buf = 0;
    for (int k0 = 0; k0 < SS; k0 += 32, buf ^= 1) {
        CPA_WAIT0();
        __syncthreads();

        if (k0 + 32 < SS) {
            const __half* src = QK + base_k + (size_t)(k0 + 32) * QKLD;
            uint32_t dstb = sK + (buf ^ 1) * 4096;
#pragma unroll
            for (int i = 0; i < 2; i++) {
                int v = tid + i * 128;
                int j = v >> 3, c = v & 7;
                cpa16(dstb + (uint32_t)(j * 128 + ((c ^ (j & 7)) << 4)),
                      src + (size_t)j * QKLD + c * 8);
            }
            if (tid < 8)
                cpa16(sM + (buf ^ 1) * 128 + tid * 16,
                      mask + b * SS + k0 + 32 + tid * 4);
        }
        CPA_COMMIT();

        const uint32_t sKb = sK + buf * 4096;
        const int* mkb = msk + buf * 32;

        // ---- S = Q @ K^T ----
        float accS[2][4][4];
#pragma unroll
        for (int mt = 0; mt < 2; mt++)
#pragma unroll
            for (int nt = 0; nt < 4; nt++)
#pragma unroll
                for (int i = 0; i < 4; i++) accS[mt][nt][i] = 0.f;

#pragma unroll
        for (int ks = 0; ks < 4; ks++) {
            int g16a = ks * 2 + (q >> 1);
            uint32_t af[2][4];
#pragma unroll
            for (int mt = 0; mt < 2; mt++) {
                ldsm4(af[mt][0], af[mt][1], af[mt][2], af[mt][3],
                      sQ + (uint32_t)(mA[mt] * 128 + ((g16a ^ (mA[mt] & 7)) << 4)));
            }
            uint32_t bf[4][2];
#pragma unroll
            for (int nt2 = 0; nt2 < 2; nt2++) {
                int nB = nt2 * 16 + (q >> 1) * 8 + r8;
                int g16 = ks * 2 + (q & 1);
                ldsm4(bf[nt2*2][0], bf[nt2*2][1], bf[nt2*2+1][0], bf[nt2*2+1][1],
                      sKb + (uint32_t)(nB * 128 + ((g16 ^ (nB & 7)) << 4)));
            }
#pragma unroll
            for (int mt = 0; mt < 2; mt++)
#pragma unroll
                for (int nt = 0; nt < 4; nt++)
                    mma_f16(accS[mt][nt], af[mt], bf[nt]);
        }

        // ---- masked scale + online softmax (l kept thread-partial) ----
        const float sc = 0.125f;   // 1/sqrt(64)
#pragma unroll
        for (int mt = 0; mt < 2; mt++) {
#pragma unroll
            for (int hh = 0; hh < 2; hh++) {
                float mloc = -INFINITY;
#pragma unroll
                for (int nt = 0; nt < 4; nt++) {
                    int c0 = nt * 8 + t2;
                    float v0 = mkb[c0]     ? accS[mt][nt][2*hh]   * sc : -1e9f;
                    float v1 = mkb[c0 + 1] ? accS[mt][nt][2*hh+1] * sc : -1e9f;
                    accS[mt][nt][2*hh] = v0; accS[mt][nt][2*hh+1] = v1;
                    mloc = fmaxf(mloc, fmaxf(v0, v1));
                }
                mloc = fmaxf(mloc, __shfl_xor_sync(0xffffffffu, mloc, 1));
                mloc = fmaxf(mloc, __shfl_xor_sync(0xffffffffu, mloc, 2));
                float mnew = fmaxf(m_[mt][hh], mloc);
                float rs = 0.f;
#pragma unroll
                for (int nt = 0; nt < 4; nt++) {
                    float p0 = __expf(accS[mt][nt][2*hh]   - mnew);
                    float p1 = __expf(accS[mt][nt][2*hh+1] - mnew);
                    accS[mt][nt][2*hh] = p0; accS[mt][nt][2*hh+1] = p1;
                    rs += p0 + p1;
                }
                float corr = __expf(m_[mt][hh] - mnew);
                l_[mt][hh] = l_[mt][hh] * corr + rs;   // thread-partial sum
                m_[mt][hh] = mnew;
#pragma unroll
                for (int nt = 0; nt < 8; nt++) {
                    accO[mt][nt][2*hh]   *= corr;
                    accO[mt][nt][2*hh+1] *= corr;
                }
            }
        }

        // ---- O += P @ K (values == K); 2 k16 steps ----
#pragma unroll
        for (int ks = 0; ks < 2; ks++) {
            uint32_t af[2][4];
#pragma unroll
            for (int mt = 0; mt < 2; mt++) {
                af[mt][0] = packh2(accS[mt][2*ks][0],   accS[mt][2*ks][1]);
                af[mt][1] = packh2(accS[mt][2*ks][2],   accS[mt][2*ks][3]);
                af[mt][2] = packh2(accS[mt][2*ks+1][0], accS[mt][2*ks+1][1]);
                af[mt][3] = packh2(accS[mt][2*ks+1][2], accS[mt][2*ks+1][3]);
            }
            int j = ks * 16 + (grp & 1) * 8 + li;
            uint32_t rowbase = sKb + (uint32_t)(j * 128);
            uint32_t bf[8][2];
#pragma unroll
            for (int nt2 = 0; nt2 < 4; nt2++) {
                int c = 2 * nt2 + (grp >> 1);
                ldsm4t(bf[2*nt2][0], bf[2*nt2][1], bf[2*nt2+1][0], bf[2*nt2+1][1],
                       rowbase + (uint32_t)(((c ^ (j & 7)) << 4)));
            }
#pragma unroll
            for (int mt = 0; mt < 2; mt++)
#pragma unroll
                for (int nt = 0; nt < 8; nt++)
                    mma_f16(accO[mt][nt], af[mt], bf[nt]);
        }
    }

    // ---- final l reduction (deferred) + normalize + store ----
#pragma unroll
    for (int mt = 0; mt < 2; mt++) {
#pragma unroll
        for (int hh = 0; hh < 2; hh++) {
            float lsum = l_[mt][hh];
            lsum += __shfl_xor_sync(0xffffffffu, lsum, 1);
            lsum += __shfl_xor_sync(0xffffffffu, lsum, 2);
            int r = wid * 32 + mt * 16 + hh * 8 + g;
            float inv = 1.0f / lsum;
            size_t rb = base_o + (size_t)(q0 + r) * DD;
#pragma unroll
            for (int nt = 0; nt < 8; nt++) {
                int c0 = nt * 8 + t2;
                *(__half2*)(O + rb + c0) =
                    __floats2half2_rn(accO[mt][nt][2*hh] * inv,
                                      accO[mt][nt][2*hh+1] * inv);
            }
        }
    }
}
#define ATTN_SMEM (16384 + 8192 + 512)

// ---------------------------------------------------------------------------
// Host driver (graph-capturable: kernel launches only)
// ---------------------------------------------------------------------------
extern "C" void kernel_launch(void* const* d_in, const int* in_sizes, int n_in,
                              void* d_out, int out_size)
{
    const float* x    = (const float*)d_in[0];
    const int*   mask = (const int*)  d_in[1];
    const float* Wq   = (const float*)d_in[2];
    const float* bq   = (const float*)d_in[3];
    const float* Wk   = (const float*)d_in[4];
    const float* bk   = (const float*)d_in[5];
    // d_in[6], d_in[7]: Wv, bv — dead code in the reference (values == keys)
    const float* Wo   = (const float*)d_in[8];
    const float* bo   = (const float*)d_in[9];
    const float* ln1g = (const float*)d_in[10];
    const float* ln1b = (const float*)d_in[11];
    const float* W1   = (const float*)d_in[12];
    const float* b1   = (const float*)d_in[13];
    const float* W2   = (const float*)d_in[14];
    const float* b2   = (const float*)d_in[15];
    const float* ln2g = (const float*)d_in[16];
    const float* ln2b = (const float*)d_in[17];
    float* out = (float*)d_out;

    __half *hid, *qk, *attn, *h2, *ffn, *wqkT, *woT, *w1T, *w2T;
    float *x2, *bqk;
    cudaGetSymbolAddress((void**)&hid,  g_hidden);
    cudaGetSymbolAddress((void**)&qk,   g_qk);
    cudaGetSymbolAddress((void**)&attn, g_attn);
    cudaGetSymbolAddress((void**)&x2,   g_x2);
    cudaGetSymbolAddress((void**)&h2,   g_h2);
    cudaGetSymbolAddress((void**)&ffn,  g_ffn);
    cudaGetSymbolAddress((void**)&wqkT, g_wqkT);
    cudaGetSymbolAddress((void**)&woT,  g_woT);
    cudaGetSymbolAddress((void**)&w1T,  g_w1T);
    cudaGetSymbolAddress((void**)&w2T,  g_w2T);
    cudaGetSymbolAddress((void**)&bqk,  g_bqk);

    cudaFuncSetAttribute(tc_gemm_kernel,
                         cudaFuncAttributeMaxDynamicSharedMemorySize, GEMM_SMEM);
    cudaFuncSetAttribute(tc_attn_kernel,
                         cudaFuncAttributeMaxDynamicSharedMemorySize, ATTN_SMEM);

    // 0) fused weight transposes (fp32 -> fp16) + bias concat
    prep_kernel<<<PREP_BLOCKS, 256>>>(Wq, Wk, Wo, W1, W2, bq, bk,
                                      wqkT, woT, w1T, w2T, bqk);

    dim3 gQK(QKLD/128, NTOK/128);
    dim3 gD (DD  /128, NTOK/128);
    dim3 gFF(DFFC/128, NTOK/128);

    // 1) LN1 -> fp16
    ln_kernel<<<NTOK, 256>>>(x, ln1g, ln1b, hid);
    // 2) fused Q+K projection (N=2048) -> fp16
    tc_gemm_kernel<<<gQK, 128, GEMM_SMEM>>>(hid, wqkT, bqk, nullptr,
                                            nullptr, qk, NTOK, QKLD, DD, 0);
    // 3) attention (values == K), fp16 tensor-core flash v5
    tc_attn_kernel<<<dim3(SS/128, HH, BB), 128, ATTN_SMEM>>>(qk, mask, attn);
    // 4) output projection + residual -> fp32
    tc_gemm_kernel<<<gD, 128, GEMM_SMEM>>>(attn, woT, bo, x,
                                           x2, nullptr, NTOK, DD, DD, 1);
    // 5) LN2 -> fp16
    ln_kernel<<<NTOK, 256>>>(x2, ln2g, ln2b, h2);
    // 6) FFN up + exact GELU -> fp16
    tc_gemm_kernel<<<gFF, 128, GEMM_SMEM>>>(h2, w1T, b1, nullptr,
                                            nullptr, ffn, NTOK, DFFC, DD, 2);
    // 7) FFN down + residual -> final fp32 output
    tc_gemm_kernel<<<gD, 128, GEMM_SMEM>>>(ffn, w2T, b2, x2,
                                           out, nullptr, NTOK, DD, DFFC, 1);
}

// round 14
// speedup vs baseline: 1.5248x; 1.5248x over previous
#include <cuda_runtime.h>
#include <cuda_fp16.h>
#include <math.h>
#include <stdint.h>

#define BB   4
#define SS   2048
#define DD   1024
#define HH   16
#define DKK  64
#define DFFC 4096
#define NTOK (BB*SS)
#define QKLD (2*DD)

// ---------------------------------------------------------------------------
// Scratch (allocation-free rule: __device__ globals)
// ---------------------------------------------------------------------------
__device__ __half g_hidden[(size_t)NTOK*DD];
__device__ __half g_qk    [(size_t)NTOK*QKLD];
__device__ __half g_attn  [(size_t)NTOK*DD];
__device__ float  g_x2    [(size_t)NTOK*DD];
__device__ __half g_h2    [(size_t)NTOK*DD];
__device__ __half g_ffn   [(size_t)NTOK*DFFC];
__device__ __half g_wqkT[(size_t)QKLD*DD];
__device__ __half g_woT [(size_t)DD*DD];
__device__ __half g_w1T [(size_t)DFFC*DD];
__device__ __half g_w2T [(size_t)DD*DFFC];
__device__ float  g_bqk [QKLD];

// ---------------------------------------------------------------------------
// Helpers
// ---------------------------------------------------------------------------
__device__ __forceinline__ uint32_t smem_u32(const void* p) {
    uint32_t a;
    asm("{ .reg .u64 t; cvta.to.shared.u64 t, %1; cvt.u32.u64 %0, t; }"
        : "=r"(a) : "l"(p));
    return a;
}

__device__ __forceinline__ void ldsm4(uint32_t& r0, uint32_t& r1,
                                      uint32_t& r2, uint32_t& r3, uint32_t addr) {
    asm volatile("ldmatrix.sync.aligned.m8n8.x4.shared.b16 {%0,%1,%2,%3}, [%4];"
                 : "=r"(r0), "=r"(r1), "=r"(r2), "=r"(r3) : "r"(addr));
}

__device__ __forceinline__ void ldsm4t(uint32_t& r0, uint32_t& r1,
                                       uint32_t& r2, uint32_t& r3, uint32_t addr) {
    asm volatile("ldmatrix.sync.aligned.m8n8.x4.trans.shared.b16 {%0,%1,%2,%3}, [%4];"
                 : "=r"(r0), "=r"(r1), "=r"(r2), "=r"(r3) : "r"(addr));
}

__device__ __forceinline__ void mma_f16(float* c, const uint32_t* a, const uint32_t* b) {
    asm volatile(
        "mma.sync.aligned.m16n8k16.row.col.f32.f16.f16.f32 "
        "{%0,%1,%2,%3}, {%4,%5,%6,%7}, {%8,%9}, {%0,%1,%2,%3};"
        : "+f"(c[0]), "+f"(c[1]), "+f"(c[2]), "+f"(c[3])
        : "r"(a[0]), "r"(a[1]), "r"(a[2]), "r"(a[3]), "r"(b[0]), "r"(b[1]));
}

__device__ __forceinline__ uint32_t packh2(float lo, float hi) {
    __half2 h = __floats2half2_rn(lo, hi);
    return *(uint32_t*)&h;
}

__device__ __forceinline__ void cpa16(uint32_t dst, const void* src) {
    asm volatile("cp.async.cg.shared.global [%0], [%1], 16;"
                 :: "r"(dst), "l"(src) : "memory");
}
#define CPA_COMMIT() asm volatile("cp.async.commit_group;" ::: "memory")
#define CPA_WAIT1()  asm volatile("cp.async.wait_group 1;"  ::: "memory")
#define CPA_WAIT0()  asm volatile("cp.async.wait_group 0;"  ::: "memory")

// ---------------------------------------------------------------------------
// Fused prep: 5 weight transposes (WT[n][k] = half(W[k][n])) + bias concat
// ---------------------------------------------------------------------------
__global__ void __launch_bounds__(256) prep_kernel(
    const float* __restrict__ Wq, const float* __restrict__ Wk,
    const float* __restrict__ Wo, const float* __restrict__ W1,
    const float* __restrict__ W2, const float* __restrict__ bq,
    const float* __restrict__ bk,
    __half* __restrict__ wqkT, __half* __restrict__ woT,
    __half* __restrict__ w1T,  __half* __restrict__ w2T,
    float* __restrict__ bqk)
{
    __shared__ float tile[32][33];
    int t = blockIdx.x;
    const float* W; __half* WT; int K, N;
    if (t < 1024)      { W = Wq; WT = wqkT;                   K = DD;   N = DD; }
    else if (t < 2048) { W = Wk; WT = wqkT + (size_t)DD*DD;   K = DD;   N = DD;   t -= 1024; }
    else if (t < 3072) { W = Wo; WT = woT;                    K = DD;   N = DD;   t -= 2048; }
    else if (t < 7168) { W = W1; WT = w1T;                    K = DD;   N = DFFC; t -= 3072; }
    else if (t < 11264){ W = W2; WT = w2T;                    K = DFFC; N = DD;   t -= 7168; }
    else {
        int i = threadIdx.x;
#pragma unroll
        for (int r = 0; r < 8; r++, i += 256) {
            if (i < DD) bqk[i] = bq[i];
            else        bqk[i] = bk[i - DD];
        }
        return;
    }
    int ntx = N >> 5;
    int kb = (t / ntx) * 32, nb = (t % ntx) * 32;
    int tx = threadIdx.x & 31, ty = threadIdx.x >> 5;
#pragma unroll
    for (int i = 0; i < 32; i += 8)
        tile[ty + i][tx] = W[(size_t)(kb + ty + i) * N + nb + tx];
    __syncthreads();
#pragma unroll
    for (int i = 0; i < 32; i += 8)
        WT[(size_t)(nb + ty + i) * K + kb + tx] = __float2half(tile[tx][ty + i]);
}
#define PREP_BLOCKS 11265

// ---------------------------------------------------------------------------
// Pipelined fp16 tensor-core GEMM (3-stage cp.async, 96KB, 2 CTA/SM)
// ---------------------------------------------------------------------------
__global__ void __launch_bounds__(128, 2) tc_gemm_kernel(
    const __half* __restrict__ A, const __half* __restrict__ BT,
    const float* __restrict__ bias, const float* __restrict__ res,
    float* __restrict__ Cf, __half* __restrict__ Ch,
    int M, int N, int K, int epi)
{
    extern __shared__ char dsm[];
    const uint32_t sAu = smem_u32(dsm);
    const uint32_t sBu = sAu + 3 * 16384;

    const int tid  = threadIdx.x;
    const int lane = tid & 31;
    const int wid  = tid >> 5;
    const int wm   = wid & 1;
    const int wn   = wid >> 1;
    const int m0   = blockIdx.y * 128;
    const int n0   = blockIdx.x * 128;

    float acc[4][8][4];
#pragma unroll
    for (int mt = 0; mt < 4; mt++)
#pragma unroll
        for (int nt = 0; nt < 8; nt++)
#pragma unroll
            for (int i = 0; i < 4; i++) acc[mt][nt][i] = 0.f;

    int r_[8], c_[8];
    uint32_t stoff[8];
#pragma unroll
    for (int i = 0; i < 8; i++) {
        int v = tid + i * 128;
        r_[i] = v >> 3;
        c_[i] = v & 7;
        stoff[i] = (uint32_t)(r_[i] * 128 + ((c_[i] ^ (r_[i] & 7)) << 4));
    }

    const __half* Ag = A  + (size_t)m0 * K;
    const __half* Bg = BT + (size_t)n0 * K;
    const int nkt = K >> 6;

#pragma unroll
    for (int p = 0; p < 2; p++) {
        uint32_t ab = sAu + p * 16384, bb = sBu + p * 16384;
        const __half* Ag2 = Ag + p * 64;
        const __half* Bg2 = Bg + p * 64;
#pragma unroll
        for (int i = 0; i < 8; i++) {
            cpa16(ab + stoff[i], Ag2 + (size_t)r_[i] * K + c_[i] * 8);
            cpa16(bb + stoff[i], Bg2 + (size_t)r_[i] * K + c_[i] * 8);
        }
        CPA_COMMIT();
    }

    const int q  = lane >> 3;
    const int r8 = lane & 7;
    int mA[4], nB[4];
#pragma unroll
    for (int mt = 0; mt < 4; mt++) mA[mt] = wm * 64 + mt * 16 + (q & 1) * 8 + r8;
#pragma unroll
    for (int nt2 = 0; nt2 < 4; nt2++) nB[nt2] = wn * 64 + nt2 * 16 + (q >> 1) * 8 + r8;

    int stg = 0;
    for (int kt = 0; kt < nkt; kt++) {
        CPA_WAIT1();
        __syncthreads();

        {
            int kt2 = kt + 2;
            if (kt2 < nkt) {
                int s2 = stg + 2; if (s2 >= 3) s2 -= 3;
                uint32_t ab = sAu + s2 * 16384, bb = sBu + s2 * 16384;
                const __half* Ag2 = Ag + kt2 * 64;
                const __half* Bg2 = Bg + kt2 * 64;
#pragma unroll
                for (int i = 0; i < 8; i++) {
                    cpa16(ab + stoff[i], Ag2 + (size_t)r_[i] * K + c_[i] * 8);
                    cpa16(bb + stoff[i], Bg2 + (size_t)r_[i] * K + c_[i] * 8);
                }
            }
            CPA_COMMIT();
        }

        const uint32_t sAb = sAu + stg * 16384;
        const uint32_t sBb = sBu + stg * 16384;
#pragma unroll
        for (int ks = 0; ks < 4; ks++) {
            uint32_t af[4][4];
#pragma unroll
            for (int mt = 0; mt < 4; mt++) {
                int g16 = ks * 2 + (q >> 1);
                uint32_t ad = sAb + (uint32_t)(mA[mt] * 128 + ((g16 ^ (mA[mt] & 7)) << 4));
                ldsm4(af[mt][0], af[mt][1], af[mt][2], af[mt][3], ad);
            }
            uint32_t bf[8][2];
#pragma unroll
            for (int nt2 = 0; nt2 < 4; nt2++) {
                int g16 = ks * 2 + (q & 1);
                uint32_t bd = sBb + (uint32_t)(nB[nt2] * 128 + ((g16 ^ (nB[nt2] & 7)) << 4));
                ldsm4(bf[nt2*2][0], bf[nt2*2][1], bf[nt2*2+1][0], bf[nt2*2+1][1], bd);
            }
#pragma unroll
            for (int mt = 0; mt < 4; mt++)
#pragma unroll
                for (int nt = 0; nt < 8; nt++)
                    mma_f16(acc[mt][nt], af[mt], bf[nt]);
        }
        stg++; if (stg == 3) stg = 0;
    }

    const int g   = lane >> 2;
    const int tig = lane & 3;
#pragma unroll
    for (int mt = 0; mt < 4; mt++) {
#pragma unroll
        for (int h = 0; h < 2; h++) {
            int row = m0 + wm * 64 + mt * 16 + h * 8 + g;
            size_t rbase = (size_t)row * N;
#pragma unroll
            for (int nt = 0; nt < 8; nt++) {
                int col = n0 + wn * 64 + nt * 8 + tig * 2;
                float v0 = acc[mt][nt][h*2 + 0] + bias[col];
                float v1 = acc[mt][nt][h*2 + 1] + bias[col + 1];
                if (epi == 2) {
                    v0 = 0.5f * v0 * (1.0f + erff(v0 * 0.70710678118654752440f));
                    v1 = 0.5f * v1 * (1.0f + erff(v1 * 0.70710678118654752440f));
                    *(__half2*)(Ch + rbase + col) = __floats2half2_rn(v0, v1);
                } else if (epi == 1) {
                    v0 += res[rbase + col];
                    v1 += res[rbase + col + 1];
                    float2 o2 = { v0, v1 };
                    *(float2*)(Cf + rbase + col) = o2;
                } else {
                    *(__half2*)(Ch + rbase + col) = __floats2half2_rn(v0, v1);
                }
            }
        }
    }
}
#define GEMM_SMEM (3*16384*2)

// ---------------------------------------------------------------------------
// LayerNorm: fp32 in -> fp16 out
// ---------------------------------------------------------------------------
__global__ void __launch_bounds__(256) ln_kernel(
    const float* __restrict__ x, const float* __restrict__ g,
    const float* __restrict__ b, __half* __restrict__ out)
{
    __shared__ float red[20];
    int t = blockIdx.x;
    int tid = threadIdx.x;
    float4 v = ((const float4*)(x + (size_t)t*DD))[tid];
    float s  = v.x + v.y + v.z + v.w;
    float s2 = v.x*v.x + v.y*v.y + v.z*v.z + v.w*v.w;
#pragma unroll
    for (int o = 16; o; o >>= 1) {
        s  += __shfl_xor_sync(0xffffffffu, s,  o);
        s2 += __shfl_xor_sync(0xffffffffu, s2, o);
    }
    int w = tid >> 5, l = tid & 31;
    if (l == 0) { red[w] = s; red[8 + w] = s2; }
    __syncthreads();
    if (tid == 0) {
        float a = 0.f, c = 0.f;
#pragma unroll
        for (int i = 0; i < 8; i++) { a += red[i]; c += red[8 + i]; }
        red[16] = a; red[17] = c;
    }
    __syncthreads();
    float mean = red[16] * (1.0f / DD);
    float var  = red[17] * (1.0f / DD) - mean * mean;
    float inv  = rsqrtf(var + 1e-5f);
    float4 gv = ((const float4*)g)[tid];
    float4 bv = ((const float4*)b)[tid];
    __half2* op = (__half2*)(out + (size_t)t*DD) + 2*tid;
    op[0] = __floats2half2_rn((v.x - mean) * inv * gv.x + bv.x,
                              (v.y - mean) * inv * gv.y + bv.y);
    op[1] = __floats2half2_rn((v.z - mean) * inv * gv.z + bv.z,
                              (v.w - mean) * inv * gv.w + bv.w);
}

// ---------------------------------------------------------------------------
// fp16 tensor-core flash attention v3 (R11-exact). values == K.
// 128q CTA tile, 4 warps x 32q; 32-key tiles; m16n8k16 fp32-acc.
// ---------------------------------------------------------------------------
__global__ void __launch_bounds__(128, 3) tc_attn_kernel(
    const __half* __restrict__ QK, const int* __restrict__ mask,
    __half* __restrict__ O)
{
    extern __shared__ char dsm[];
    __half* Qs = (__half*)dsm;                  // [128][64]
    __half* Kj = (__half*)(dsm + 16384);        // [2][32*64]
    int*    msk = (int*)(dsm + 24576);          // [2][32]

    const int b = blockIdx.z, h = blockIdx.y;
    const int q0 = blockIdx.x * 128;
    const int tid = threadIdx.x;
    const int lane = tid & 31, wid = tid >> 5;
    const size_t base_q = (size_t)b * SS * QKLD + (size_t)h * DKK;
    const size_t base_k = base_q + DD;
    const size_t base_o = (size_t)b * SS * DD + (size_t)h * DKK;

    const uint32_t sQ = smem_u32(Qs);
    const uint32_t sK = smem_u32(Kj);
    const uint32_t sM = smem_u32(msk);

    // Q tile: 128 rows x 8 chunks (16B)
#pragma unroll
    for (int i = 0; i < 8; i++) {
        int v = tid + i * 128;
        int r = v >> 3, c = v & 7;
        float4 val = *(const float4*)(QK + base_q + (size_t)(q0 + r) * QKLD + c * 8);
        *(float4*)((char*)Qs + r * 128 + ((c ^ (r & 7)) << 4)) = val;
    }

    // prologue: async K tile 0 + mask 0
#pragma unroll
    for (int i = 0; i < 2; i++) {
        int v = tid + i * 128;
        int j = v >> 3, c = v & 7;
        cpa16(sK + (uint32_t)(j * 128 + ((c ^ (j & 7)) << 4)),
              QK + base_k + (size_t)j * QKLD + c * 8);
    }
    if (tid < 8) cpa16(sM + tid * 16, mask + b * SS + tid * 4);
    CPA_COMMIT();

    const int q  = lane >> 3, r8 = lane & 7;
    const int g  = lane >> 2, tig = lane & 3;
    const int t2 = 2 * tig;
    const int grp = lane >> 3, li = lane & 7;
    int mA[2];
    mA[0] = wid * 32 + (q & 1) * 8 + r8;
    mA[1] = mA[0] + 16;

    float m_[2][2], l_[2][2];
#pragma unroll
    for (int mt = 0; mt < 2; mt++)
#pragma unroll
        for (int hh = 0; hh < 2; hh++) { m_[mt][hh] = -INFINITY; l_[mt][hh] = 0.f; }
    float accO[2][8][4];
#pragma unroll
    for (int mt = 0; mt < 2; mt++)
#pragma unroll
        for (int nt = 0; nt < 8; nt++)
#pragma unroll
            for (int i = 0; i < 4; i++) accO[mt][nt][i] = 0.f;

    int buf = 0;
    for (int k0 = 0; k0 < SS; k0 += 32, buf ^= 1) {
        CPA_WAIT0();
        __syncthreads();

        if (k0 + 32 < SS) {
            const __half* src = QK + base_k + (size_t)(k0 + 32) * QKLD;
            uint32_t dstb = sK + (buf ^ 1) * 4096;
#pragma unroll
            for (int i = 0; i < 2; i++) {
                int v = tid + i * 128;
                int j = v >> 3, c = v & 7;
                cpa16(dstb + (uint32_t)(j * 128 + ((c ^ (j & 7)) << 4)),
                      src + (size_t)j * QKLD + c * 8);
            }
            if (tid < 8)
                cpa16(sM + (buf ^ 1) * 128 + tid * 16,
                      mask + b * SS + k0 + 32 + tid * 4);
        }
        CPA_COMMIT();

        const uint32_t sKb = sK + buf * 4096;
        const int* mkb = msk + buf * 32;

        // ---- S = Q @ K^T ----
        float accS[2][4][4];
#pragma unroll
        for (int mt = 0; mt < 2; mt++)
#pragma unroll
            for (int nt = 0; nt < 4; nt++)
#pragma unroll
                for (int i = 0; i < 4; i++) accS[mt][nt][i] = 0.f;

#pragma unroll
        for (int ks = 0; ks < 4; ks++) {
            int g16a = ks * 2 + (q >> 1);
            uint32_t af[2][4];
#pragma unroll
            for (int mt = 0; mt < 2; mt++) {
                ldsm4(af[mt][0], af[mt][1], af[mt][2], af[mt][3],
                      sQ + (uint32_t)(mA[mt] * 128 + ((g16a ^ (mA[mt] & 7)) << 4)));
            }
            uint32_t bf[4][2];
#pragma unroll
            for (int nt2 = 0; nt2 < 2; nt2++) {
                int nB = nt2 * 16 + (q >> 1) * 8 + r8;
                int g16 = ks * 2 + (q & 1);
                ldsm4(bf[nt2*2][0], bf[nt2*2][1], bf[nt2*2+1][0], bf[nt2*2+1][1],
                      sKb + (uint32_t)(nB * 128 + ((g16 ^ (nB & 7)) << 4)));
            }
#pragma unroll
            for (int mt = 0; mt < 2; mt++)
#pragma unroll
                for (int nt = 0; nt < 4; nt++)
                    mma_f16(accS[mt][nt], af[mt], bf[nt]);
        }

        // ---- masked scale + online softmax ----
        const float sc = 0.125f;   // 1/sqrt(64)
#pragma unroll
        for (int mt = 0; mt < 2; mt++) {
#pragma unroll
            for (int hh = 0; hh < 2; hh++) {
                float mloc = -INFINITY;
#pragma unroll
                for (int nt = 0; nt < 4; nt++) {
                    int c0 = nt * 8 + t2;
                    float v0 = mkb[c0]     ? accS[mt][nt][2*hh]   * sc : -1e9f;
                    float v1 = mkb[c0 + 1] ? accS[mt][nt][2*hh+1] * sc : -1e9f;
                    accS[mt][nt][2*hh] = v0; accS[mt][nt][2*hh+1] = v1;
                    mloc = fmaxf(mloc, fmaxf(v0, v1));
                }
                mloc = fmaxf(mloc, __shfl_xor_sync(0xffffffffu, mloc, 1));
                mloc = fmaxf(mloc, __shfl_xor_sync(0xffffffffu, mloc, 2));
                float mnew = fmaxf(m_[mt][hh], mloc);
                float rs = 0.f;
#pragma unroll
                for (int nt = 0; nt < 4; nt++) {
                    float p0 = __expf(accS[mt][nt][2*hh]   - mnew);
                    float p1 = __expf(accS[mt][nt][2*hh+1] - mnew);
                    accS[mt][nt][2*hh] = p0; accS[mt][nt][2*hh+1] = p1;
                    rs += p0 + p1;
                }
                rs += __shfl_xor_sync(0xffffffffu, rs, 1);
                rs += __shfl_xor_sync(0xffffffffu, rs, 2);
                float corr = __expf(m_[mt][hh] - mnew);
                l_[mt][hh] = l_[mt][hh] * corr + rs;
                m_[mt][hh] = mnew;
#pragma unroll
                for (int nt = 0; nt < 8; nt++) {
                    accO[mt][nt][2*hh]   *= corr;
                    accO[mt][nt][2*hh+1] *= corr;
                }
            }
        }

        // ---- O += P @ K (values == K); 2 k16 steps ----
#pragma unroll
        for (int ks = 0; ks < 2; ks++) {
            uint32_t af[2][4];
#pragma unroll
            for (int mt = 0; mt < 2; mt++) {
                af[mt][0] = packh2(accS[mt][2*ks][0],   accS[mt][2*ks][1]);
                af[mt][1] = packh2(accS[mt][2*ks][2],   accS[mt][2*ks][3]);
                af[mt][2] = packh2(accS[mt][2*ks+1][0], accS[mt][2*ks+1][1]);
                af[mt][3] = packh2(accS[mt][2*ks+1][2], accS[mt][2*ks+1][3]);
            }
            int j = ks * 16 + (grp & 1) * 8 + li;
            uint32_t rowbase = sKb + (uint32_t)(j * 128);
            uint32_t bf[8][2];
#pragma unroll
            for (int nt2 = 0; nt2 < 4; nt2++) {
                int c = 2 * nt2 + (grp >> 1);
                ldsm4t(bf[2*nt2][0], bf[2*nt2][1], bf[2*nt2+1][0], bf[2*nt2+1][1],
                       rowbase + (uint32_t)(((c ^ (j & 7)) << 4)));
            }
#pragma unroll
            for (int mt = 0; mt < 2; mt++)
#pragma unroll
                for (int nt = 0; nt < 8; nt++)
                    mma_f16(accO[mt][nt], af[mt], bf[nt]);
        }
    }

    // ---- normalize + store (half) ----
#pragma unroll
    for (int mt = 0; mt < 2; mt++) {
#pragma unroll
        for (int hh = 0; hh < 2; hh++) {
            int r = wid * 32 + mt * 16 + hh * 8 + g;
            float inv = 1.0f / l_[mt][hh];
            size_t rb = base_o + (size_t)(q0 + r) * DD;
#pragma unroll
            for (int nt = 0; nt < 8; nt++) {
                int c0 = nt * 8 + t2;
                *(__half2*)(O + rb + c0) =
                    __floats2half2_rn(accO[mt][nt][2*hh] * inv,
                                      accO[mt][nt][2*hh+1] * inv);
            }
        }
    }
}
#define ATTN_SMEM (16384 + 8192 + 512)

// ---------------------------------------------------------------------------
// Host driver (graph-capturable: kernel launches only)
// ---------------------------------------------------------------------------
extern "C" void kernel_launch(void* const* d_in, const int* in_sizes, int n_in,
                              void* d_out, int out_size)
{
    const float* x    = (const float*)d_in[0];
    const int*   mask = (const int*)  d_in[1];
    const float* Wq   = (const float*)d_in[2];
    const float* bq   = (const float*)d_in[3];
    const float* Wk   = (const float*)d_in[4];
    const float* bk   = (const float*)d_in[5];
    // d_in[6], d_in[7]: Wv, bv — dead code in the reference (values == keys)
    const float* Wo   = (const float*)d_in[8];
    const float* bo   = (const float*)d_in[9];
    const float* ln1g = (const float*)d_in[10];
    const float* ln1b = (const float*)d_in[11];
    const float* W1   = (const float*)d_in[12];
    const float* b1   = (const float*)d_in[13];
    const float* W2   = (const float*)d_in[14];
    const float* b2   = (const float*)d_in[15];
    const float* ln2g = (const float*)d_in[16];
    const float* ln2b = (const float*)d_in[17];
    float* out = (float*)d_out;

    __half *hid, *qk, *attn, *h2, *ffn, *wqkT, *woT, *w1T, *w2T;
    float *x2, *bqk;
    cudaGetSymbolAddress((void**)&hid,  g_hidden);
    cudaGetSymbolAddress((void**)&qk,   g_qk);
    cudaGetSymbolAddress((void**)&attn, g_attn);
    cudaGetSymbolAddress((void**)&x2,   g_x2);
    cudaGetSymbolAddress((void**)&h2,   g_h2);
    cudaGetSymbolAddress((void**)&ffn,  g_ffn);
    cudaGetSymbolAddress((void**)&wqkT, g_wqkT);
    cudaGetSymbolAddress((void**)&woT,  g_woT);
    cudaGetSymbolAddress((void**)&w1T,  g_w1T);
    cudaGetSymbolAddress((void**)&w2T,  g_w2T);
    cudaGetSymbolAddress((void**)&bqk,  g_bqk);

    cudaFuncSetAttribute(tc_gemm_kernel,
                         cudaFuncAttributeMaxDynamicSharedMemorySize, GEMM_SMEM);
    cudaFuncSetAttribute(tc_attn_kernel,
                         cudaFuncAttributeMaxDynamicSharedMemorySize, ATTN_SMEM);

    // 0) fused weight transposes (fp32 -> fp16) + bias concat
    prep_kernel<<<PREP_BLOCKS, 256>>>(Wq, Wk, Wo, W1, W2, bq, bk,
                                      wqkT, woT, w1T, w2T, bqk);

    dim3 gQK(QKLD/128, NTOK/128);
    dim3 gD (DD  /128, NTOK/128);
    dim3 gFF(DFFC/128, NTOK/128);

    // 1) LN1 -> fp16
    ln_kernel<<<NTOK, 256>>>(x, ln1g, ln1b, hid);
    // 2) fused Q+K projection (N=2048) -> fp16
    tc_gemm_kernel<<<gQK, 128, GEMM_SMEM>>>(hid, wqkT, bqk, nullptr,
                                            nullptr, qk, NTOK, QKLD, DD, 0);
    // 3) attention (values == K), fp16 tensor-core flash v3
    tc_attn_kernel<<<dim3(SS/128, HH, BB), 128, ATTN_SMEM>>>(qk, mask, attn);
    // 4) output projection + residual -> fp32
    tc_gemm_kernel<<<gD, 128, GEMM_SMEM>>>(attn, woT, bo, x,
                                           x2, nullptr, NTOK, DD, DD, 1);
    // 5) LN2 -> fp16
    ln_kernel<<<NTOK, 256>>>(x2, ln2g, ln2b, h2);
    // 6) FFN up + exact GELU -> fp16
    tc_gemm_kernel<<<gFF, 128, GEMM_SMEM>>>(h2, w1T, b1, nullptr,
                                            nullptr, ffn, NTOK, DFFC, DD, 2);
    // 7) FFN down + residual -> final fp32 output
    tc_gemm_kernel<<<gD, 128, GEMM_SMEM>>>(ffn, w2T, b2, x2,
                                           out, nullptr, NTOK, DD, DFFC, 1);
}

// round 15
// speedup vs baseline: 1.5552x; 1.0199x over previous
#include <cuda_runtime.h>
#include <cuda_fp16.h>
#include <math.h>
#include <stdint.h>

#define BB   4
#define SS   2048
#define DD   1024
#define HH   16
#define DKK  64
#define DFFC 4096
#define NTOK (BB*SS)
#define QKLD (2*DD)

// ---------------------------------------------------------------------------
// Scratch (allocation-free rule: __device__ globals)
// ---------------------------------------------------------------------------
__device__ __half g_hidden[(size_t)NTOK*DD];
__device__ __half g_qk    [(size_t)NTOK*QKLD];
__device__ __half g_attn  [(size_t)NTOK*DD];
__device__ float  g_x2    [(size_t)NTOK*DD];
__device__ __half g_h2    [(size_t)NTOK*DD];
__device__ __half g_ffn   [(size_t)NTOK*DFFC];
__device__ __half g_wqkT[(size_t)QKLD*DD];
__device__ __half g_woT [(size_t)DD*DD];
__device__ __half g_w1T [(size_t)DFFC*DD];
__device__ __half g_w2T [(size_t)DD*DFFC];
__device__ float  g_bqk [QKLD];

// ---------------------------------------------------------------------------
// Helpers
// ---------------------------------------------------------------------------
__device__ __forceinline__ uint32_t smem_u32(const void* p) {
    uint32_t a;
    asm("{ .reg .u64 t; cvta.to.shared.u64 t, %1; cvt.u32.u64 %0, t; }"
        : "=r"(a) : "l"(p));
    return a;
}

__device__ __forceinline__ void ldsm4(uint32_t& r0, uint32_t& r1,
                                      uint32_t& r2, uint32_t& r3, uint32_t addr) {
    asm volatile("ldmatrix.sync.aligned.m8n8.x4.shared.b16 {%0,%1,%2,%3}, [%4];"
                 : "=r"(r0), "=r"(r1), "=r"(r2), "=r"(r3) : "r"(addr));
}

__device__ __forceinline__ void ldsm4t(uint32_t& r0, uint32_t& r1,
                                       uint32_t& r2, uint32_t& r3, uint32_t addr) {
    asm volatile("ldmatrix.sync.aligned.m8n8.x4.trans.shared.b16 {%0,%1,%2,%3}, [%4];"
                 : "=r"(r0), "=r"(r1), "=r"(r2), "=r"(r3) : "r"(addr));
}

__device__ __forceinline__ void mma_f16(float* c, const uint32_t* a, const uint32_t* b) {
    asm volatile(
        "mma.sync.aligned.m16n8k16.row.col.f32.f16.f16.f32 "
        "{%0,%1,%2,%3}, {%4,%5,%6,%7}, {%8,%9}, {%0,%1,%2,%3};"
        : "+f"(c[0]), "+f"(c[1]), "+f"(c[2]), "+f"(c[3])
        : "r"(a[0]), "r"(a[1]), "r"(a[2]), "r"(a[3]), "r"(b[0]), "r"(b[1]));
}

__device__ __forceinline__ uint32_t packh2(float lo, float hi) {
    __half2 h = __floats2half2_rn(lo, hi);
    return *(uint32_t*)&h;
}

__device__ __forceinline__ void cpa16(uint32_t dst, const void* src) {
    asm volatile("cp.async.cg.shared.global [%0], [%1], 16;"
                 :: "r"(dst), "l"(src) : "memory");
}
#define CPA_COMMIT() asm volatile("cp.async.commit_group;" ::: "memory")
#define CPA_WAIT1()  asm volatile("cp.async.wait_group 1;"  ::: "memory")
#define CPA_WAIT0()  asm volatile("cp.async.wait_group 0;"  ::: "memory")

// ---------------------------------------------------------------------------
// Fused prep: 5 weight transposes (WT[n][k] = half(W[k][n])) + bias concat
// ---------------------------------------------------------------------------
__global__ void __launch_bounds__(256) prep_kernel(
    const float* __restrict__ Wq, const float* __restrict__ Wk,
    const float* __restrict__ Wo, const float* __restrict__ W1,
    const float* __restrict__ W2, const float* __restrict__ bq,
    const float* __restrict__ bk,
    __half* __restrict__ wqkT, __half* __restrict__ woT,
    __half* __restrict__ w1T,  __half* __restrict__ w2T,
    float* __restrict__ bqk)
{
    __shared__ float tile[32][33];
    int t = blockIdx.x;
    const float* W; __half* WT; int K, N;
    if (t < 1024)      { W = Wq; WT = wqkT;                   K = DD;   N = DD; }
    else if (t < 2048) { W = Wk; WT = wqkT + (size_t)DD*DD;   K = DD;   N = DD;   t -= 1024; }
    else if (t < 3072) { W = Wo; WT = woT;                    K = DD;   N = DD;   t -= 2048; }
    else if (t < 7168) { W = W1; WT = w1T;                    K = DD;   N = DFFC; t -= 3072; }
    else if (t < 11264){ W = W2; WT = w2T;                    K = DFFC; N = DD;   t -= 7168; }
    else {
        int i = threadIdx.x;
#pragma unroll
        for (int r = 0; r < 8; r++, i += 256) {
            if (i < DD) bqk[i] = bq[i];
            else        bqk[i] = bk[i - DD];
        }
        return;
    }
    int ntx = N >> 5;
    int kb = (t / ntx) * 32, nb = (t % ntx) * 32;
    int tx = threadIdx.x & 31, ty = threadIdx.x >> 5;
#pragma unroll
    for (int i = 0; i < 32; i += 8)
        tile[ty + i][tx] = W[(size_t)(kb + ty + i) * N + nb + tx];
    __syncthreads();
#pragma unroll
    for (int i = 0; i < 32; i += 8)
        WT[(size_t)(nb + ty + i) * K + kb + tx] = __float2half(tile[tx][ty + i]);
}
#define PREP_BLOCKS 11265

// ---------------------------------------------------------------------------
// Pipelined fp16 tensor-core GEMM (R14-exact: 3-stage cp.async, 96KB, 2 CTA/SM)
// ---------------------------------------------------------------------------
__global__ void __launch_bounds__(128, 2) tc_gemm_kernel(
    const __half* __restrict__ A, const __half* __restrict__ BT,
    const float* __restrict__ bias, const float* __restrict__ res,
    float* __restrict__ Cf, __half* __restrict__ Ch,
    int M, int N, int K, int epi)
{
    extern __shared__ char dsm[];
    const uint32_t sAu = smem_u32(dsm);
    const uint32_t sBu = sAu + 3 * 16384;

    const int tid  = threadIdx.x;
    const int lane = tid & 31;
    const int wid  = tid >> 5;
    const int wm   = wid & 1;
    const int wn   = wid >> 1;
    const int m0   = blockIdx.y * 128;
    const int n0   = blockIdx.x * 128;

    float acc[4][8][4];
#pragma unroll
    for (int mt = 0; mt < 4; mt++)
#pragma unroll
        for (int nt = 0; nt < 8; nt++)
#pragma unroll
            for (int i = 0; i < 4; i++) acc[mt][nt][i] = 0.f;

    int r_[8], c_[8];
    uint32_t stoff[8];
#pragma unroll
    for (int i = 0; i < 8; i++) {
        int v = tid + i * 128;
        r_[i] = v >> 3;
        c_[i] = v & 7;
        stoff[i] = (uint32_t)(r_[i] * 128 + ((c_[i] ^ (r_[i] & 7)) << 4));
    }

    const __half* Ag = A  + (size_t)m0 * K;
    const __half* Bg = BT + (size_t)n0 * K;
    const int nkt = K >> 6;

#pragma unroll
    for (int p = 0; p < 2; p++) {
        uint32_t ab = sAu + p * 16384, bb = sBu + p * 16384;
        const __half* Ag2 = Ag + p * 64;
        const __half* Bg2 = Bg + p * 64;
#pragma unroll
        for (int i = 0; i < 8; i++) {
            cpa16(ab + stoff[i], Ag2 + (size_t)r_[i] * K + c_[i] * 8);
            cpa16(bb + stoff[i], Bg2 + (size_t)r_[i] * K + c_[i] * 8);
        }
        CPA_COMMIT();
    }

    const int q  = lane >> 3;
    const int r8 = lane & 7;
    int mA[4], nB[4];
#pragma unroll
    for (int mt = 0; mt < 4; mt++) mA[mt] = wm * 64 + mt * 16 + (q & 1) * 8 + r8;
#pragma unroll
    for (int nt2 = 0; nt2 < 4; nt2++) nB[nt2] = wn * 64 + nt2 * 16 + (q >> 1) * 8 + r8;

    int stg = 0;
    for (int kt = 0; kt < nkt; kt++) {
        CPA_WAIT1();
        __syncthreads();

        {
            int kt2 = kt + 2;
            if (kt2 < nkt) {
                int s2 = stg + 2; if (s2 >= 3) s2 -= 3;
                uint32_t ab = sAu + s2 * 16384, bb = sBu + s2 * 16384;
                const __half* Ag2 = Ag + kt2 * 64;
                const __half* Bg2 = Bg + kt2 * 64;
#pragma unroll
                for (int i = 0; i < 8; i++) {
                    cpa16(ab + stoff[i], Ag2 + (size_t)r_[i] * K + c_[i] * 8);
                    cpa16(bb + stoff[i], Bg2 + (size_t)r_[i] * K + c_[i] * 8);
                }
            }
            CPA_COMMIT();
        }

        const uint32_t sAb = sAu + stg * 16384;
        const uint32_t sBb = sBu + stg * 16384;
#pragma unroll
        for (int ks = 0; ks < 4; ks++) {
            uint32_t af[4][4];
#pragma unroll
            for (int mt = 0; mt < 4; mt++) {
                int g16 = ks * 2 + (q >> 1);
                uint32_t ad = sAb + (uint32_t)(mA[mt] * 128 + ((g16 ^ (mA[mt] & 7)) << 4));
                ldsm4(af[mt][0], af[mt][1], af[mt][2], af[mt][3], ad);
            }
            uint32_t bf[8][2];
#pragma unroll
            for (int nt2 = 0; nt2 < 4; nt2++) {
                int g16 = ks * 2 + (q & 1);
                uint32_t bd = sBb + (uint32_t)(nB[nt2] * 128 + ((g16 ^ (nB[nt2] & 7)) << 4));
                ldsm4(bf[nt2*2][0], bf[nt2*2][1], bf[nt2*2+1][0], bf[nt2*2+1][1], bd);
            }
#pragma unroll
            for (int mt = 0; mt < 4; mt++)
#pragma unroll
                for (int nt = 0; nt < 8; nt++)
                    mma_f16(acc[mt][nt], af[mt], bf[nt]);
        }
        stg++; if (stg == 3) stg = 0;
    }

    const int g   = lane >> 2;
    const int tig = lane & 3;
#pragma unroll
    for (int mt = 0; mt < 4; mt++) {
#pragma unroll
        for (int h = 0; h < 2; h++) {
            int row = m0 + wm * 64 + mt * 16 + h * 8 + g;
            size_t rbase = (size_t)row * N;
#pragma unroll
            for (int nt = 0; nt < 8; nt++) {
                int col = n0 + wn * 64 + nt * 8 + tig * 2;
                float v0 = acc[mt][nt][h*2 + 0] + bias[col];
                float v1 = acc[mt][nt][h*2 + 1] + bias[col + 1];
                if (epi == 2) {
                    v0 = 0.5f * v0 * (1.0f + erff(v0 * 0.70710678118654752440f));
                    v1 = 0.5f * v1 * (1.0f + erff(v1 * 0.70710678118654752440f));
                    *(__half2*)(Ch + rbase + col) = __floats2half2_rn(v0, v1);
                } else if (epi == 1) {
                    v0 += res[rbase + col];
                    v1 += res[rbase + col + 1];
                    float2 o2 = { v0, v1 };
                    *(float2*)(Cf + rbase + col) = o2;
                } else {
                    *(__half2*)(Ch + rbase + col) = __floats2half2_rn(v0, v1);
                }
            }
        }
    }
}
#define GEMM_SMEM (3*16384*2)

// ---------------------------------------------------------------------------
// LayerNorm: fp32 in -> fp16 out (unchanged)
// ---------------------------------------------------------------------------
__global__ void __launch_bounds__(256) ln_kernel(
    const float* __restrict__ x, const float* __restrict__ g,
    const float* __restrict__ b, __half* __restrict__ out)
{
    __shared__ float red[20];
    int t = blockIdx.x;
    int tid = threadIdx.x;
    float4 v = ((const float4*)(x + (size_t)t*DD))[tid];
    float s  = v.x + v.y + v.z + v.w;
    float s2 = v.x*v.x + v.y*v.y + v.z*v.z + v.w*v.w;
#pragma unroll
    for (int o = 16; o; o >>= 1) {
        s  += __shfl_xor_sync(0xffffffffu, s,  o);
        s2 += __shfl_xor_sync(0xffffffffu, s2, o);
    }
    int w = tid >> 5, l = tid & 31;
    if (l == 0) { red[w] = s; red[8 + w] = s2; }
    __syncthreads();
    if (tid == 0) {
        float a = 0.f, c = 0.f;
#pragma unroll
        for (int i = 0; i < 8; i++) { a += red[i]; c += red[8 + i]; }
        red[16] = a; red[17] = c;
    }
    __syncthreads();
    float mean = red[16] * (1.0f / DD);
    float var  = red[17] * (1.0f / DD) - mean * mean;
    float inv  = rsqrtf(var + 1e-5f);
    float4 gv = ((const float4*)g)[tid];
    float4 bv = ((const float4*)b)[tid];
    __half2* op = (__half2*)(out + (size_t)t*DD) + 2*tid;
    op[0] = __floats2half2_rn((v.x - mean) * inv * gv.x + bv.x,
                              (v.y - mean) * inv * gv.y + bv.y);
    op[1] = __floats2half2_rn((v.z - mean) * inv * gv.z + bv.z,
                              (v.w - mean) * inv * gv.w + bv.w);
}

// ---------------------------------------------------------------------------
// fp16 tensor-core flash attention v6. values == K (reference quirk).
// R11/R14 base (4 warps x 32q, 32-key tiles) with two softmax-chain cuts:
//  (1) deferred l-reduction: thread-partial sums carry the corr recurrence
//      (corr row-uniform + linearity); cross-lane shfl-sum once in epilogue.
//  (2) log2-domain: logits scaled by 0.125*log2e (folded into the existing
//      scale multiply), exp via exp2f -> drops the FMUL inside every __expf.
// ---------------------------------------------------------------------------
__global__ void __launch_bounds__(128, 3) tc_attn_kernel(
    const __half* __restrict__ QK, const int* __restrict__ mask,
    __half* __restrict__ O)
{
    extern __shared__ char dsm[];
    __half* Qs = (__half*)dsm;                  // [128][64]
    __half* Kj = (__half*)(dsm + 16384);        // [2][32*64]
    int*    msk = (int*)(dsm + 24576);          // [2][32]

    const int b = blockIdx.z, h = blockIdx.y;
    const int q0 = blockIdx.x * 128;
    const int tid = threadIdx.x;
    const int lane = tid & 31, wid = tid >> 5;
    const size_t base_q = (size_t)b * SS * QKLD + (size_t)h * DKK;
    const size_t base_k = base_q + DD;
    const size_t base_o = (size_t)b * SS * DD + (size_t)h * DKK;

    const uint32_t sQ = smem_u32(Qs);
    const uint32_t sK = smem_u32(Kj);
    const uint32_t sM = smem_u32(msk);

    // Q tile: 128 rows x 8 chunks (16B)
#pragma unroll
    for (int i = 0; i < 8; i++) {
        int v = tid + i * 128;
        int r = v >> 3, c = v & 7;
        float4 val = *(const float4*)(QK + base_q + (size_t)(q0 + r) * QKLD + c * 8);
        *(float4*)((char*)Qs + r * 128 + ((c ^ (r & 7)) << 4)) = val;
    }

    // prologue: async K tile 0 + mask 0
#pragma unroll
    for (int i = 0; i < 2; i++) {
        int v = tid + i * 128;
        int j = v >> 3, c = v & 7;
        cpa16(sK + (uint32_t)(j * 128 + ((c ^ (j & 7)) << 4)),
              QK + base_k + (size_t)j * QKLD + c * 8);
    }
    if (tid < 8) cpa16(sM + tid * 16, mask + b * SS + tid * 4);
    CPA_COMMIT();

    const int q  = lane >> 3, r8 = lane & 7;
    const int g  = lane >> 2, tig = lane & 3;
    const int t2 = 2 * tig;
    const int grp = lane >> 3, li = lane & 7;
    int mA[2];
    mA[0] = wid * 32 + (q & 1) * 8 + r8;
    mA[1] = mA[0] + 16;

    float m_[2][2], l_[2][2];
#pragma unroll
    for (int mt = 0; mt < 2; mt++)
#pragma unroll
        for (int hh = 0; hh < 2; hh++) { m_[mt][hh] = -INFINITY; l_[mt][hh] = 0.f; }
    float accO[2][8][4];
#pragma unroll
    for (int mt = 0; mt < 2; mt++)
#pragma unroll
        for (int nt = 0; nt < 8; nt++)
#pragma unroll
            for (int i = 0; i < 4; i++) accO[mt][nt][i] = 0.f;

    int buf = 0;
    for (int k0 = 0; k0 < SS; k0 += 32, buf ^= 1) {
        CPA_WAIT0();
        __syncthreads();

        if (k0 + 32 < SS) {
            const __half* src = QK + base_k + (size_t)(k0 + 32) * QKLD;
            uint32_t dstb = sK + (buf ^ 1) * 4096;
#pragma unroll
            for (int i = 0; i < 2; i++) {
                int v = tid + i * 128;
                int j = v >> 3, c = v & 7;
                cpa16(dstb + (uint32_t)(j * 128 + ((c ^ (j & 7)) << 4)),
                      src + (size_t)j * QKLD + c * 8);
            }
            if (tid < 8)
                cpa16(sM + (buf ^ 1) * 128 + tid * 16,
                      mask + b * SS + k0 + 32 + tid * 4);
        }
        CPA_COMMIT();

        const uint32_t sKb = sK + buf * 4096;
        const int* mkb = msk + buf * 32;

        // ---- S = Q @ K^T ----
        float accS[2][4][4];
#pragma unroll
        for (int mt = 0; mt < 2; mt++)
#pragma unroll
            for (int nt = 0; nt < 4; nt++)
#pragma unroll
                for (int i = 0; i < 4; i++) accS[mt][nt][i] = 0.f;

#pragma unroll
        for (int ks = 0; ks < 4; ks++) {
            int g16a = ks * 2 + (q >> 1);
            uint32_t af[2][4];
#pragma unroll
            for (int mt = 0; mt < 2; mt++) {
                ldsm4(af[mt][0], af[mt][1], af[mt][2], af[mt][3],
                      sQ + (uint32_t)(mA[mt] * 128 + ((g16a ^ (mA[mt] & 7)) << 4)));
            }
            uint32_t bf[4][2];
#pragma unroll
            for (int nt2 = 0; nt2 < 2; nt2++) {
                int nB = nt2 * 16 + (q >> 1) * 8 + r8;
                int g16 = ks * 2 + (q & 1);
                ldsm4(bf[nt2*2][0], bf[nt2*2][1], bf[nt2*2+1][0], bf[nt2*2+1][1],
                      sKb + (uint32_t)(nB * 128 + ((g16 ^ (nB & 7)) << 4)));
            }
#pragma unroll
            for (int mt = 0; mt < 2; mt++)
#pragma unroll
                for (int nt = 0; nt < 4; nt++)
                    mma_f16(accS[mt][nt], af[mt], bf[nt]);
        }

        // ---- masked scale + online softmax (log2-domain, thread-partial l) ----
        const float sc = 0.18033688011112042f;   // 0.125 * log2(e)
#pragma unroll
        for (int mt = 0; mt < 2; mt++) {
#pragma unroll
            for (int hh = 0; hh < 2; hh++) {
                float mloc = -INFINITY;
#pragma unroll
                for (int nt = 0; nt < 4; nt++) {
                    int c0 = nt * 8 + t2;
                    float v0 = mkb[c0]     ? accS[mt][nt][2*hh]   * sc : -1.5e9f;
                    float v1 = mkb[c0 + 1] ? accS[mt][nt][2*hh+1] * sc : -1.5e9f;
                    accS[mt][nt][2*hh] = v0; accS[mt][nt][2*hh+1] = v1;
                    mloc = fmaxf(mloc, fmaxf(v0, v1));
                }
                mloc = fmaxf(mloc, __shfl_xor_sync(0xffffffffu, mloc, 1));
                mloc = fmaxf(mloc, __shfl_xor_sync(0xffffffffu, mloc, 2));
                float mnew = fmaxf(m_[mt][hh], mloc);
                float rs = 0.f;
#pragma unroll
                for (int nt = 0; nt < 4; nt++) {
                    float p0 = exp2f(accS[mt][nt][2*hh]   - mnew);
                    float p1 = exp2f(accS[mt][nt][2*hh+1] - mnew);
                    accS[mt][nt][2*hh] = p0; accS[mt][nt][2*hh+1] = p1;
                    rs += p0 + p1;
                }
                float corr = exp2f(m_[mt][hh] - mnew);
                l_[mt][hh] = l_[mt][hh] * corr + rs;   // thread-partial sum
                m_[mt][hh] = mnew;
#pragma unroll
                for (int nt = 0; nt < 8; nt++) {
                    accO[mt][nt][2*hh]   *= corr;
                    accO[mt][nt][2*hh+1] *= corr;
                }
            }
        }

        // ---- O += P @ K (values == K); 2 k16 steps ----
#pragma unroll
        for (int ks = 0; ks < 2; ks++) {
            uint32_t af[2][4];
#pragma unroll
            for (int mt = 0; mt < 2; mt++) {
                af[mt][0] = packh2(accS[mt][2*ks][0],   accS[mt][2*ks][1]);
                af[mt][1] = packh2(accS[mt][2*ks][2],   accS[mt][2*ks][3]);
                af[mt][2] = packh2(accS[mt][2*ks+1][0], accS[mt][2*ks+1][1]);
                af[mt][3] = packh2(accS[mt][2*ks+1][2], accS[mt][2*ks+1][3]);
            }
            int j = ks * 16 + (grp & 1) * 8 + li;
            uint32_t rowbase = sKb + (uint32_t)(j * 128);
            uint32_t bf[8][2];
#pragma unroll
            for (int nt2 = 0; nt2 < 4; nt2++) {
                int c = 2 * nt2 + (grp >> 1);
                ldsm4t(bf[2*nt2][0], bf[2*nt2][1], bf[2*nt2+1][0], bf[2*nt2+1][1],
                       rowbase + (uint32_t)(((c ^ (j & 7)) << 4)));
            }
#pragma unroll
            for (int mt = 0; mt < 2; mt++)
#pragma unroll
                for (int nt = 0; nt < 8; nt++)
                    mma_f16(accO[mt][nt], af[mt], bf[nt]);
        }
    }

    // ---- final l reduction (deferred) + normalize + store ----
#pragma unroll
    for (int mt = 0; mt < 2; mt++) {
#pragma unroll
        for (int hh = 0; hh < 2; hh++) {
            float lsum = l_[mt][hh];
            lsum += __shfl_xor_sync(0xffffffffu, lsum, 1);
            lsum += __shfl_xor_sync(0xffffffffu, lsum, 2);
            int r = wid * 32 + mt * 16 + hh * 8 + g;
            float inv = 1.0f / lsum;
            size_t rb = base_o + (size_t)(q0 + r) * DD;
#pragma unroll
            for (int nt = 0; nt < 8; nt++) {
                int c0 = nt * 8 + t2;
                *(__half2*)(O + rb + c0) =
                    __floats2half2_rn(accO[mt][nt][2*hh] * inv,
                                      accO[mt][nt][2*hh+1] * inv);
            }
        }
    }
}
#define ATTN_SMEM (16384 + 8192 + 512)

// ---------------------------------------------------------------------------
// Host driver (graph-capturable: kernel launches only)
// ---------------------------------------------------------------------------
extern "C" void kernel_launch(void* const* d_in, const int* in_sizes, int n_in,
                              void* d_out, int out_size)
{
    const float* x    = (const float*)d_in[0];
    const int*   mask = (const int*)  d_in[1];
    const float* Wq   = (const float*)d_in[2];
    const float* bq   = (const float*)d_in[3];
    const float* Wk   = (const float*)d_in[4];
    const float* bk   = (const float*)d_in[5];
    // d_in[6], d_in[7]: Wv, bv — dead code in the reference (values == keys)
    const float* Wo   = (const float*)d_in[8];
    const float* bo   = (const float*)d_in[9];
    const float* ln1g = (const float*)d_in[10];
    const float* ln1b = (const float*)d_in[11];
    const float* W1   = (const float*)d_in[12];
    const float* b1   = (const float*)d_in[13];
    const float* W2   = (const float*)d_in[14];
    const float* b2   = (const float*)d_in[15];
    const float* ln2g = (const float*)d_in[16];
    const float* ln2b = (const float*)d_in[17];
    float* out = (float*)d_out;

    __half *hid, *qk, *attn, *h2, *ffn, *wqkT, *woT, *w1T, *w2T;
    float *x2, *bqk;
    cudaGetSymbolAddress((void**)&hid,  g_hidden);
    cudaGetSymbolAddress((void**)&qk,   g_qk);
    cudaGetSymbolAddress((void**)&attn, g_attn);
    cudaGetSymbolAddress((void**)&x2,   g_x2);
    cudaGetSymbolAddress((void**)&h2,   g_h2);
    cudaGetSymbolAddress((void**)&ffn,  g_ffn);
    cudaGetSymbolAddress((void**)&wqkT, g_wqkT);
    cudaGetSymbolAddress((void**)&woT,  g_woT);
    cudaGetSymbolAddress((void**)&w1T,  g_w1T);
    cudaGetSymbolAddress((void**)&w2T,  g_w2T);
    cudaGetSymbolAddress((void**)&bqk,  g_bqk);

    cudaFuncSetAttribute(tc_gemm_kernel,
                         cudaFuncAttributeMaxDynamicSharedMemorySize, GEMM_SMEM);
    cudaFuncSetAttribute(tc_attn_kernel,
                         cudaFuncAttributeMaxDynamicSharedMemorySize, ATTN_SMEM);

    // 0) fused weight transposes (fp32 -> fp16) + bias concat
    prep_kernel<<<PREP_BLOCKS, 256>>>(Wq, Wk, Wo, W1, W2, bq, bk,
                                      wqkT, woT, w1T, w2T, bqk);

    dim3 gQK(QKLD/128, NTOK/128);
    dim3 gD (DD  /128, NTOK/128);
    dim3 gFF(DFFC/128, NTOK/128);

    // 1) LN1 -> fp16
    ln_kernel<<<NTOK, 256>>>(x, ln1g, ln1b, hid);
    // 2) fused Q+K projection (N=2048) -> fp16
    tc_gemm_kernel<<<gQK, 128, GEMM_SMEM>>>(hid, wqkT, bqk, nullptr,
                                            nullptr, qk, NTOK, QKLD, DD, 0);
    // 3) attention (values == K), fp16 tensor-core flash v6
    tc_attn_kernel<<<dim3(SS/128, HH, BB), 128, ATTN_SMEM>>>(qk, mask, attn);
    // 4) output projection + residual -> fp32
    tc_gemm_kernel<<<gD, 128, GEMM_SMEM>>>(attn, woT, bo, x,
                                           x2, nullptr, NTOK, DD, DD, 1);
    // 5) LN2 -> fp16
    ln_kernel<<<NTOK, 256>>>(x2, ln2g, ln2b, h2);
    // 6) FFN up + exact GELU -> fp16
    tc_gemm_kernel<<<gFF, 128, GEMM_SMEM>>>(h2, w1T, b1, nullptr,
                                            nullptr, ffn, NTOK, DFFC, DD, 2);
    // 7) FFN down + residual -> final fp32 output
    tc_gemm_kernel<<<gD, 128, GEMM_SMEM>>>(ffn, w2T, b2, x2,
                                           out, nullptr, NTOK, DD, DFFC, 1);
}